// round 17
// baseline (speedup 1.0000x reference)
#include <cuda_runtime.h>

// ---------------------------------------------------------------------------
// SpMiddleFHD. Sparsity: 0.355% occupancy => ~3.7K non-self neighbor pairs.
// Submanifold convs = dense self-term GEMV + tiny sparse pair corrections.
// Pair probing gated by a 1.5MB L2-resident occupancy bitmap. The 189MB
// output zero-fill runs as a memset node on a side stream (copy-engine path,
// no SM contention), overlapped with the conv chain; after the join, conv3
// scatters atomics DIRECTLY into out, and an idempotent relu pass fixes up
// the ~1.1% touched voxels (L2-hot). No accumulator, no flags, no finalize.
// All scratch invariants restored every call (graph-replay safe).
// ---------------------------------------------------------------------------

namespace {
constexpr int kB  = 2;
constexpr int kDZ = 41, kHY = 400, kWX = 352;
constexpr int kGD = kDZ + 2, kGH = kHY + 2, kGW = kWX + 2;
constexpr int kN  = 40000;
constexpr int kDO = 21, kHO = 200, kWO = 176;
constexpr int kGridCells = kB * kGD * kGH * kGW;      // 12,238,488
constexpr int kBitWords  = (kGridCells + 31) / 32;    // ~1.53MB bitmap
constexpr int kMaxPairs  = kN * 27;
}

__device__ unsigned short g_grid[kGridCells];         // idx+1 (0 empty)
__device__ unsigned int   g_bit[kBitWords];           // occupancy bitmap
__device__ int  g_np;                                 // pair counter
__device__ int2 g_pairs[kMaxPairs];                   // {n, (k<<16)|idx}
__device__ __align__(16) float g_x1[kN * 16];         // pre-relu conv1 out
__device__ __align__(16) float g_x2[kN * 16];         // pre-relu conv2 out

__device__ __forceinline__ int cell_of(int4 c) {
    return ((c.x * kGD + c.y + 1) * kGH + c.z + 1) * kGW + c.w + 1;
}

// ---------------------------------------------------------------------------
__global__ void k_scatter(const int4* __restrict__ coors) {
    int n = blockIdx.x * blockDim.x + threadIdx.x;
    if (n == 0) g_np = 0;
    if (n >= kN) return;
    int4 c = __ldg(&coors[n]);
    int cell = cell_of(c);
    g_grid[cell] = (unsigned short)(n + 1);
    atomicOr(&g_bit[cell >> 5], 1u << (cell & 31));
}

// Thread per (point, offset<13). Bitmap gate (L2-resident); uint16 grid read
// on hit only. Each hit (n,m,j) also emits (m,n,26-j).
__global__ void k_pairs_probe(const int4* __restrict__ coors) {
    int t = blockIdx.x * blockDim.x + threadIdx.x;
    if (t >= kN * 13) return;
    int n = t / 13, j = t - n * 13;
    int4 c = __ldg(&coors[n]);
    int dk = j / 9, dy = (j / 3) % 3, dx = j % 3;
    int cell = ((c.x * kGD + c.y + dk) * kGH + c.z + dy) * kGW + c.w + dx;
    if (!((g_bit[cell >> 5] >> (cell & 31)) & 1u)) return;
    int m = (int)g_grid[cell] - 1;
    if (m >= 0) {
        int base = atomicAdd(&g_np, 2);
        g_pairs[base]     = make_int2(n, (j << 16) | m);
        g_pairs[base + 1] = make_int2(m, ((26 - j) << 16) | n);
    }
}

// ---------------------------------------------------------------------------
// Dense conv1 self-term: x1[n] = feat[n] . W1[13] (pre-relu store).
// W1[13] hoisted into registers, reused for 16 points/warp.
__global__ void __launch_bounds__(256) k_dense1(const float4* __restrict__ fv,
                                                const float4* __restrict__ w1v) {
    int w    = blockIdx.x * (blockDim.x >> 5) + (threadIdx.x >> 5);
    int lane = threadIdx.x & 31;
    int n0   = w * 16;
    if (n0 >= kN) return;
    int dq = lane & 3, cg = lane >> 2;

    float4 wv[16];
    const float4* wb = &w1v[13 * 512 + dq];
    #pragma unroll
    for (int e = 0; e < 16; e++) wv[e] = __ldg(&wb[(cg * 16 + e) * 4]);

    #pragma unroll
    for (int rep = 0; rep < 4; rep++) {
        int nb = n0 + rep * 4;
        float4 acc[4];
        #pragma unroll
        for (int p = 0; p < 4; p++) {
            float fs[16];
            #pragma unroll
            for (int q = 0; q < 4; q++) {
                float4 f = __ldcg(&fv[(nb + p) * 32 + cg * 4 + q]);
                fs[q*4+0] = f.x; fs[q*4+1] = f.y;
                fs[q*4+2] = f.z; fs[q*4+3] = f.w;
            }
            float4 a = make_float4(0.f, 0.f, 0.f, 0.f);
            #pragma unroll
            for (int e = 0; e < 16; e++) {
                float f = fs[e];
                a.x += f * wv[e].x; a.y += f * wv[e].y;
                a.z += f * wv[e].z; a.w += f * wv[e].w;
            }
            acc[p] = a;
        }
        #pragma unroll
        for (int p = 0; p < 4; p++) {
            #pragma unroll
            for (int o = 4; o < 32; o <<= 1) {
                acc[p].x += __shfl_xor_sync(0xffffffffu, acc[p].x, o);
                acc[p].y += __shfl_xor_sync(0xffffffffu, acc[p].y, o);
                acc[p].z += __shfl_xor_sync(0xffffffffu, acc[p].z, o);
                acc[p].w += __shfl_xor_sync(0xffffffffu, acc[p].w, o);
            }
            if (cg == 0)
                reinterpret_cast<float4*>(g_x1)[(nb + p) * 4 + dq] = acc[p];
        }
    }
}

// Sparse conv1 corrections: warp per pair, grid-stride.
__global__ void k_pairs1(const float4* __restrict__ fv,
                         const float4* __restrict__ w1v) {
    int wflat  = blockIdx.x * (blockDim.x >> 5) + (threadIdx.x >> 5);
    int nwarps = gridDim.x * (blockDim.x >> 5);
    int lane   = threadIdx.x & 31;
    int dq = lane & 3, cg = lane >> 2;
    int np = g_np;

    for (int p = wflat; p < np; p += nwarps) {
        int2 pr = g_pairs[p];
        int n = pr.x, k = pr.y >> 16, idx = pr.y & 0xffff;

        float fs[16];
        #pragma unroll
        for (int q = 0; q < 4; q++) {
            float4 f = __ldcg(&fv[idx * 32 + cg * 4 + q]);
            fs[q*4+0] = f.x; fs[q*4+1] = f.y; fs[q*4+2] = f.z; fs[q*4+3] = f.w;
        }

        float4 acc = make_float4(0.f, 0.f, 0.f, 0.f);
        const float4* wb = &w1v[k * 512 + dq];
        #pragma unroll
        for (int e = 0; e < 16; e++) {
            float4 wv = __ldg(&wb[(cg * 16 + e) * 4]);
            float f = fs[e];
            acc.x += f * wv.x; acc.y += f * wv.y;
            acc.z += f * wv.z; acc.w += f * wv.w;
        }
        #pragma unroll
        for (int o = 4; o < 32; o <<= 1) {
            acc.x += __shfl_xor_sync(0xffffffffu, acc.x, o);
            acc.y += __shfl_xor_sync(0xffffffffu, acc.y, o);
            acc.z += __shfl_xor_sync(0xffffffffu, acc.z, o);
            acc.w += __shfl_xor_sync(0xffffffffu, acc.w, o);
        }
        if (cg == 0) {
            float* dst = &g_x1[n * 16 + dq * 4];
            atomicAdd(dst + 0, acc.x); atomicAdd(dst + 1, acc.y);
            atomicAdd(dst + 2, acc.z); atomicAdd(dst + 3, acc.w);
        }
    }
}

// ---------------------------------------------------------------------------
// Dense conv2 self-term; clears this point's grid cell + bitmap bit.
__global__ void k_dense2(const float* __restrict__ W2,
                         const int4* __restrict__ coors) {
    int t = blockIdx.x * blockDim.x + threadIdx.x;
    int n = t >> 4, d = t & 15;
    if (n >= kN) return;

    const float* xr = &g_x1[n * 16];
    const float* wr = &W2[13 * 256 + d];
    float acc = 0.f;
    #pragma unroll
    for (int cc = 0; cc < 16; cc++)
        acc += fmaxf(xr[cc], 0.f) * __ldg(&wr[cc * 16]);
    g_x2[n * 16 + d] = acc;

    if (d == 0) {
        int4 c = __ldg(&coors[n]);
        int cell = cell_of(c);
        g_grid[cell] = 0;
        atomicAnd(&g_bit[cell >> 5], ~(1u << (cell & 31)));
    }
}

// Sparse conv2 corrections: half-warp per pair, grid-stride.
__global__ void k_pairs2(const float* __restrict__ W2) {
    int hw  = (blockIdx.x * blockDim.x + threadIdx.x) >> 4;
    int nhw = (gridDim.x * blockDim.x) >> 4;
    int d   = threadIdx.x & 15;
    int np  = g_np;

    for (int p = hw; p < np; p += nhw) {
        int2 pr = g_pairs[p];
        int n = pr.x, k = pr.y >> 16, idx = pr.y & 0xffff;
        const float* xr = &g_x1[idx * 16];
        const float* wr = &W2[k * 256 + d];
        float acc = 0.f;
        #pragma unroll
        for (int cc = 0; cc < 16; cc++)
            acc += fmaxf(xr[cc], 0.f) * __ldg(&wr[cc * 16]);
        atomicAdd(&g_x2[n * 16 + d], acc);
    }
}

// ---------------------------------------------------------------------------
// conv3 (16->32) + strided scatter of atomics DIRECTLY into out (pre-zeroed
// by the overlapped memset). Warp per (n, dk); lane = output channel.
__global__ void k_conv3(const int4* __restrict__ coors,
                        const float* __restrict__ W3,
                        float* __restrict__ out) {
    int n    = blockIdx.x * (blockDim.x >> 5) + (threadIdx.x >> 5);
    int lane = threadIdx.x & 31;
    int dk   = blockIdx.y;
    if (n >= kN) return;

    int4 c = __ldg(&coors[n]);
    int oz = c.y + 1 - dk;
    if (oz < 0 || (oz & 1)) return;
    int pz = oz >> 1;
    if (pz >= kDO) return;

    const float4* x2v = reinterpret_cast<const float4*>(&g_x2[n * 16]);
    float xs[16];
    #pragma unroll
    for (int q = 0; q < 4; q++) {
        float4 v = x2v[q];
        xs[q*4+0] = fmaxf(v.x, 0.f); xs[q*4+1] = fmaxf(v.y, 0.f);
        xs[q*4+2] = fmaxf(v.z, 0.f); xs[q*4+3] = fmaxf(v.w, 0.f);
    }

    for (int dy = 0; dy < 3; dy++) {
        int oy = c.z + 1 - dy;
        if (oy < 0 || (oy & 1)) continue;
        int py = oy >> 1;
        if (py >= kHO) continue;
        for (int dx = 0; dx < 3; dx++) {
            int ox = c.w + 1 - dx;
            if (ox < 0 || (ox & 1)) continue;
            int px = ox >> 1;
            if (px >= kWO) continue;
            int k    = dk * 9 + dy * 3 + dx;
            int base = ((c.x * kDO + pz) * kHO + py) * kWO + px;
            float v = 0.f;
            #pragma unroll
            for (int cc = 0; cc < 16; cc++)
                v += xs[cc] * __ldg(&W3[(k * 16 + cc) * 32 + lane]);
            atomicAdd(&out[(size_t)base * 32 + lane], v);
        }
    }
}

// Idempotent relu over exactly the touched voxels (relu∘relu = relu;
// duplicate warps write identical values). L2-hot after the atomics.
__global__ void k_relu_touched(const int4* __restrict__ coors,
                               float* __restrict__ out) {
    int n    = blockIdx.x * (blockDim.x >> 5) + (threadIdx.x >> 5);
    int lane = threadIdx.x & 31;
    int dk   = blockIdx.y;
    if (n >= kN) return;

    int4 c = __ldg(&coors[n]);
    int oz = c.y + 1 - dk;
    if (oz < 0 || (oz & 1)) return;
    int pz = oz >> 1;
    if (pz >= kDO) return;

    for (int dy = 0; dy < 3; dy++) {
        int oy = c.z + 1 - dy;
        if (oy < 0 || (oy & 1)) continue;
        int py = oy >> 1;
        if (py >= kHO) continue;
        for (int dx = 0; dx < 3; dx++) {
            int ox = c.w + 1 - dx;
            if (ox < 0 || (ox & 1)) continue;
            int px = ox >> 1;
            if (px >= kWO) continue;
            int base = ((c.x * kDO + pz) * kHO + py) * kWO + px;
            size_t o = (size_t)base * 32 + lane;
            out[o] = fmaxf(out[o], 0.f);
        }
    }
}

// ---------------------------------------------------------------------------
extern "C" void kernel_launch(void* const* d_in, const int* in_sizes, int n_in,
                              void* d_out, int out_size) {
    const float* feat  = (const float*)d_in[0];
    const int4*  coors = (const int4*) d_in[1];
    const float* W1    = (const float*)d_in[2];
    const float* W2    = (const float*)d_in[3];
    const float* W3    = (const float*)d_in[4];
    float*       out   = (float*)d_out;
    (void)in_sizes; (void)n_in;

    static cudaStream_t side = nullptr;
    static cudaEvent_t  efork = nullptr, ezero = nullptr;
    if (!side) {
        cudaStreamCreateWithFlags(&side, cudaStreamNonBlocking);
        cudaEventCreateWithFlags(&efork, cudaEventDisableTiming);
        cudaEventCreateWithFlags(&ezero, cudaEventDisableTiming);
    }

    dim3 g3((kN + 7) / 8, 3);

    // Side stream: memset node zeroes the 189MB output (no SM contention),
    // overlapped with the conv chain; joined before the atomic scatter.
    cudaEventRecord(efork, 0);
    cudaStreamWaitEvent(side, efork, 0);
    cudaMemsetAsync(out, 0, (size_t)out_size * sizeof(float), side);
    cudaEventRecord(ezero, side);

    k_scatter     <<<(kN + 255) / 256, 256>>>(coors);
    k_pairs_probe <<<(kN * 13 + 255) / 256, 256>>>(coors);
    k_dense1      <<<(kN / 16 + 7) / 8, 256>>>((const float4*)feat,
                                               (const float4*)W1);
    k_pairs1      <<<1024, 256>>>((const float4*)feat, (const float4*)W1);
    k_dense2      <<<(kN * 16 + 255) / 256, 256>>>(W2, coors);
    k_pairs2      <<<512, 256>>>(W2);

    cudaStreamWaitEvent(0, ezero, 0);
    k_conv3        <<<g3, 256>>>(coors, W3, out);
    k_relu_touched <<<g3, 256>>>(coors, out);
}